// round 3
// baseline (speedup 1.0000x reference)
#include <cuda_runtime.h>
#include <cstdint>

#define HDIM  128
#define WDIM  128
#define N_PIX 16384          // H*W
#define BATCH 64

#define NSM        148
#define SCAN_GRID  (NSM * 8)    // one full wave at 256 thr/block

// Scratch (allocation-free: __device__ globals, zero-initialized at load;
// the fused kernel re-zeros them every launch so each launch starts clean).
__device__ unsigned long long g_spikemask[N_PIX];               // bit b set if S0[b, n] != 0
__device__ float              g_global[BATCH * (size_t)N_PIX];  // g[b][m], 4 MB

// ---------------------------------------------------------------------------
// Kernel 1: build per-pixel spike bitmask (mask assumed pre-zeroed).
// 131072 threads: n = tid & 16383 (coalesced), c = tid >> 14 selects an
// 8-batch chunk -> 8-load latency chain instead of 64.
// ---------------------------------------------------------------------------
__global__ void __launch_bounds__(256) prep_kernel(const float* __restrict__ S0) {
    int tid = blockIdx.x * blockDim.x + threadIdx.x;   // grid = 512*256 = 131072
    int n = tid & (N_PIX - 1);
    int c = tid >> 14;                                 // 0..7
    const float* base = S0 + (size_t)(c * 8) * N_PIX + n;

    unsigned m8 = 0;
    #pragma unroll
    for (int j = 0; j < 8; j++) {
        float s = __ldg(base + (size_t)j * N_PIX);     // coalesced in n
        if (s != 0.0f) m8 |= (1u << j);
    }
    if (m8)
        atomicOr(&g_spikemask[n], (unsigned long long)m8 << (8 * c));
}

// ---------------------------------------------------------------------------
// Kernel 2: stream the 1 GiB matrix (contiguous chunk per block, 8 independent
// 128B loads in flight per thread), scatter nonzeros into g.
// ---------------------------------------------------------------------------
__device__ __forceinline__ void handle_nz(size_t idx, float val) {
    int n = (int)(idx >> 14);        // row
    int m = (int)(idx & 16383);      // col
    unsigned long long mask = g_spikemask[n];
    while (mask) {
        int b = __ffsll((long long)mask) - 1;
        atomicAdd(&g_global[(size_t)b * N_PIX + m], val);
        mask &= mask - 1;
    }
}

__device__ __forceinline__ void check4(const float4& v, size_t base) {
    unsigned nz = __float_as_uint(v.x) | __float_as_uint(v.y) |
                  __float_as_uint(v.z) | __float_as_uint(v.w);
    if (nz != 0u) {
        if (v.x != 0.0f) handle_nz(base + 0, v.x);
        if (v.y != 0.0f) handle_nz(base + 1, v.y);
        if (v.z != 0.0f) handle_nz(base + 2, v.z);
        if (v.w != 0.0f) handle_nz(base + 3, v.w);
    }
}

__global__ void __launch_bounds__(256) scan_kernel(const float4* __restrict__ M4) {
    const size_t total = (size_t)N_PIX * N_PIX / 4;               // 67,108,864 float4
    const size_t per_block = (total + gridDim.x - 1) / gridDim.x; // contiguous chunk
    size_t begin = (size_t)blockIdx.x * per_block;
    size_t end   = begin + per_block;
    if (end > total) end = total;

    // 8 independent loads per thread per iteration; block walks its chunk in
    // contiguous 32 KB steps (256 thr * 8 * 16B) for DRAM row locality.
    size_t i = begin + threadIdx.x;
    for (; i + 7 * 256 < end; i += 8 * 256) {
        float4 v0 = __ldcs(M4 + i + 0 * 256);
        float4 v1 = __ldcs(M4 + i + 1 * 256);
        float4 v2 = __ldcs(M4 + i + 2 * 256);
        float4 v3 = __ldcs(M4 + i + 3 * 256);
        float4 v4 = __ldcs(M4 + i + 4 * 256);
        float4 v5 = __ldcs(M4 + i + 5 * 256);
        float4 v6 = __ldcs(M4 + i + 6 * 256);
        float4 v7 = __ldcs(M4 + i + 7 * 256);
        check4(v0, (i + 0 * 256) * 4);
        check4(v1, (i + 1 * 256) * 4);
        check4(v2, (i + 2 * 256) * 4);
        check4(v3, (i + 3 * 256) * 4);
        check4(v4, (i + 4 * 256) * 4);
        check4(v5, (i + 5 * 256) * 4);
        check4(v6, (i + 6 * 256) * 4);
        check4(v7, (i + 7 * 256) * 4);
    }
    for (; i < end; i += 256) {
        float4 v = __ldcs(M4 + i);
        check4(v, i * 4);
    }
}

// ---------------------------------------------------------------------------
// Kernel 3: box convs (separable circular window sums) + fused update.
// Two blocks per batch (64 rows + 3-row halo). Epilogue re-zeros the scratch
// (g_global slice + spikemask slice) for the next launch.
// ---------------------------------------------------------------------------
#define ROWS_PER_BLK 64
#define HALO 3
#define SROWS (ROWS_PER_BLK + 2 * HALO)   // 70

__global__ void fused_kernel(
    const float* __restrict__ V0, const float* __restrict__ S0,
    const float* __restrict__ U,
    const float* __restrict__ exc_w_p, const float* __restrict__ inh_w_p,
    const float* __restrict__ p_decay, const float* __restrict__ p_thr,
    const float* __restrict__ p_reset, const float* __restrict__ p_split,
    const float* __restrict__ p_excl,  const float* __restrict__ p_excg,
    const float* __restrict__ p_inhl,  const float* __restrict__ p_inhg,
    const float* __restrict__ p_drop,  const float* __restrict__ p_lower,
    float* __restrict__ out)
{
    extern __shared__ float sm[];
    float* rs7 = sm;                  // horizontal 7-window sums, SROWS x 128
    float* rs5 = sm + SROWS * WDIM;   // horizontal 5-window sums

    const int b  = blockIdx.x >> 1;
    const int r0 = (blockIdx.x & 1) * ROWS_PER_BLK;   // first output row
    const int t  = threadIdx.x;
    const float* S = S0 + (size_t)b * N_PIX;

    // Phase A: horizontal circular window sums for rows r0-3 .. r0+66 (wrapped)
    for (int i = t; i < SROWS * WDIM; i += blockDim.x) {
        int lr = i >> 7, w = i & 127;
        int h = (r0 - HALO + lr) & (HDIM - 1);
        const float* row = S + (h << 7);
        float s7 = 0.f, s5 = 0.f;
        #pragma unroll
        for (int d = -3; d <= 3; d++) {
            float v = row[(w + d) & 127];
            s7 += v;
            if (d >= -2 && d <= 2) s5 += v;
        }
        rs7[i] = s7;
        rs5[i] = s5;
    }
    __syncthreads();

    const float decay = *p_decay, thr = *p_thr, rst = *p_reset, split = *p_split;
    const float excl = *p_excl, excg = *p_excg, inhl = *p_inhl, inhg = *p_inhg;
    const float drop = *p_drop, lower = *p_lower;
    const float w7 = *exc_w_p, w5 = *inh_w_p;       // 1/49, 1/25 (exact f32 from ref)
    const float oms = 1.0f - split;

    float* outV = out;
    float* outS = out + (size_t)BATCH * N_PIX;
    float* outY = out + (size_t)2 * BATCH * N_PIX;

    for (int i = t; i < ROWS_PER_BLK * WDIM; i += blockDim.x) {
        int lr = i >> 7, w = i & 127;
        int h = r0 + lr;

        // Phase B: vertical circular window sums from smem (conflict-free)
        float c7 = 0.f, c5 = 0.f;
        #pragma unroll
        for (int d = -3; d <= 3; d++) {
            int sr = lr + HALO + d;                   // 0..SROWS-1
            c7 += rs7[(sr << 7) + w];
            if (d >= -2 && d <= 2) c5 += rs5[(sr << 7) + w];
        }

        size_t gi = (size_t)b * N_PIX + (h << 7) + w;
        float v0 = V0[gi], u = U[gi], gg = g_global[gi];
        g_global[gi] = 0.0f;          // re-zero scratch for next launch

        // V = decay*V0 + input_split*U   (non-fused, matches XLA mul+add)
        float V = __fadd_rn(__fmul_rn(decay, v0), __fmul_rn(split, u));
        bool active = V > lower;

        // lateral = excl*conv7 + inhl*conv5 + excg*g + inhg*g
        float conv7 = __fmul_rn(c7, w7);
        float conv5 = __fmul_rn(c5, w5);
        float lat = __fadd_rn(__fmul_rn(excl, conv7), __fmul_rn(inhl, conv5));
        lat = __fadd_rn(lat, __fmul_rn(excg, gg));
        lat = __fadd_rn(lat, __fmul_rn(inhg, gg));

        if (active)
            V = __fadd_rn(__fadd_rn(V, __fmul_rn(oms, u)), lat);
        V = fminf(fmaxf(V, -2.0f), 2.0f);

        float spike = (V > thr) ? 1.0f : 0.0f;

        // deterministic dropout mask: frac(h + 0.7*w) > drop  (non-fused fp32)
        float a = __fadd_rn((float)h, __fmul_rn(0.7f, (float)w));
        float frac = __fsub_rn(a, floorf(a));
        float mask = (frac > drop) ? 1.0f : 0.0f;
        float sp = __fmul_rn(spike, mask);

        if (sp > 0.0f) V = rst;

        float y = fminf(fmaxf(__fmul_rn(__fadd_rn(V, 1.0f), 0.5f), 0.0f), 1.0f);
        y = __fadd_rn(y, __fmul_rn(0.5f, sp));
        y = fminf(fmaxf(y, 0.0f), 1.0f);

        outV[gi] = V;
        outS[gi] = sp;
        outY[gi] = y;
    }

    // Re-zero this block's slice of the spike mask (128 words per block)
    for (int i = t; i < N_PIX / (BATCH * 2); i += blockDim.x)
        g_spikemask[blockIdx.x * (N_PIX / (BATCH * 2)) + i] = 0ULL;
}

// ---------------------------------------------------------------------------
extern "C" void kernel_launch(void* const* d_in, const int* in_sizes, int n_in,
                              void* d_out, int out_size) {
    const float* V0    = (const float*)d_in[0];
    const float* S0    = (const float*)d_in[1];
    const float* U     = (const float*)d_in[2];
    const float* exc_w = (const float*)d_in[3];
    const float* inh_w = (const float*)d_in[4];
    const float* M     = (const float*)d_in[5];
    const float* decay = (const float*)d_in[6];
    const float* thr   = (const float*)d_in[7];
    const float* reset = (const float*)d_in[8];
    const float* split = (const float*)d_in[9];
    const float* excl  = (const float*)d_in[10];
    const float* excg  = (const float*)d_in[11];
    const float* inhl  = (const float*)d_in[12];
    const float* inhg  = (const float*)d_in[13];
    const float* drop  = (const float*)d_in[14];
    const float* lower = (const float*)d_in[15];
    float* out = (float*)d_out;

    prep_kernel<<<512, 256>>>(S0);                       // mask build only
    scan_kernel<<<SCAN_GRID, 256>>>((const float4*)M);

    int smem = 2 * SROWS * WDIM * (int)sizeof(float);    // 71,680 B
    cudaFuncSetAttribute(fused_kernel, cudaFuncAttributeMaxDynamicSharedMemorySize, smem);
    fused_kernel<<<BATCH * 2, 512, smem>>>(V0, S0, U, exc_w, inh_w,
                                           decay, thr, reset, split,
                                           excl, excg, inhl, inhg, drop, lower,
                                           out);
}

// round 4
// speedup vs baseline: 1.0014x; 1.0014x over previous
#include <cuda_runtime.h>
#include <cstdint>

#define HDIM  128
#define WDIM  128
#define N_PIX 16384          // H*W
#define BATCH 64

#define NSM        148
#define SCAN_BLKS  (NSM * 8)     // 1184: one full wave at 256 thr/block

// Scratch (allocation-free: __device__ globals, zero-initialized at load;
// the fused kernel re-zeros them every launch so each launch starts clean).
__device__ unsigned long long g_spikemask[N_PIX];               // bit b set if S0[b, n] != 0
__device__ float              g_global[BATCH * (size_t)N_PIX];  // g[b][m], 4 MB

// ---------------------------------------------------------------------------
// Kernel 1: build per-pixel spike bitmask (mask pre-zeroed by prior launch).
// 262144 threads: n = tid & 16383 (coalesced), c = tid >> 14 selects a
// 4-batch chunk -> short latency chains, high parallelism.
// ---------------------------------------------------------------------------
__global__ void __launch_bounds__(256) prep_kernel(const float* __restrict__ S0) {
    int tid = blockIdx.x * blockDim.x + threadIdx.x;   // grid = 1024*256 = 262144
    int n = tid & (N_PIX - 1);
    int c = tid >> 14;                                 // 0..15
    const float* base = S0 + (size_t)(c * 4) * N_PIX + n;

    unsigned m4 = 0;
    #pragma unroll
    for (int j = 0; j < 4; j++) {
        float s = __ldg(base + (size_t)j * N_PIX);     // coalesced in n
        if (s != 0.0f) m4 |= (1u << j);
    }
    if (m4)
        atomicOr(&g_spikemask[n], (unsigned long long)m4 << (4 * c));
}

// ---------------------------------------------------------------------------
// Kernel 2: stream the 1 GiB matrix, scatter nonzeros into g.
// Grid-interleaved / block-contiguous: each block owns a contiguous 16 KB
// tile (1024 float4) per iteration; the whole grid sweeps one contiguous
// ~19 MB window that slides uniformly through the matrix.
// ---------------------------------------------------------------------------
__device__ __forceinline__ void handle_nz(size_t idx, float val) {
    int n = (int)(idx >> 14);        // row
    int m = (int)(idx & 16383);      // col
    unsigned long long mask = g_spikemask[n];
    while (mask) {
        int b = __ffsll((long long)mask) - 1;
        atomicAdd(&g_global[(size_t)b * N_PIX + m], val);
        mask &= mask - 1;
    }
}

__device__ __forceinline__ void check4(const float4& v, size_t base) {
    unsigned nz = __float_as_uint(v.x) | __float_as_uint(v.y) |
                  __float_as_uint(v.z) | __float_as_uint(v.w);
    if (nz != 0u) {
        if (v.x != 0.0f) handle_nz(base + 0, v.x);
        if (v.y != 0.0f) handle_nz(base + 1, v.y);
        if (v.z != 0.0f) handle_nz(base + 2, v.z);
        if (v.w != 0.0f) handle_nz(base + 3, v.w);
    }
}

__global__ void __launch_bounds__(256) scan_kernel(const float4* __restrict__ M4) {
    const size_t total = (size_t)N_PIX * N_PIX / 4;      // 67,108,864 float4
    const size_t step  = (size_t)SCAN_BLKS * 1024;       // grid advance per iter

    size_t b = (size_t)blockIdx.x * 1024 + threadIdx.x;
    for (; b + 768 < total; b += step) {
        float4 v0 = __ldcs(M4 + b + 0 * 256);
        float4 v1 = __ldcs(M4 + b + 1 * 256);
        float4 v2 = __ldcs(M4 + b + 2 * 256);
        float4 v3 = __ldcs(M4 + b + 3 * 256);
        check4(v0, (b + 0 * 256) * 4);
        check4(v1, (b + 1 * 256) * 4);
        check4(v2, (b + 2 * 256) * 4);
        check4(v3, (b + 3 * 256) * 4);
    }
    for (; b < total; b += 256) {                        // safety tail
        float4 v = __ldcs(M4 + b);
        check4(v, b * 4);
    }
}

// ---------------------------------------------------------------------------
// Kernel 3: box convs (separable circular window sums) + fused update.
// Two blocks per batch (64 rows + 3-row halo). Epilogue re-zeros the scratch
// (g_global slice + spikemask slice) for the next launch.
// ---------------------------------------------------------------------------
#define ROWS_PER_BLK 64
#define HALO 3
#define SROWS (ROWS_PER_BLK + 2 * HALO)   // 70

__global__ void fused_kernel(
    const float* __restrict__ V0, const float* __restrict__ S0,
    const float* __restrict__ U,
    const float* __restrict__ exc_w_p, const float* __restrict__ inh_w_p,
    const float* __restrict__ p_decay, const float* __restrict__ p_thr,
    const float* __restrict__ p_reset, const float* __restrict__ p_split,
    const float* __restrict__ p_excl,  const float* __restrict__ p_excg,
    const float* __restrict__ p_inhl,  const float* __restrict__ p_inhg,
    const float* __restrict__ p_drop,  const float* __restrict__ p_lower,
    float* __restrict__ out)
{
    extern __shared__ float sm[];
    float* rs7 = sm;                  // horizontal 7-window sums, SROWS x 128
    float* rs5 = sm + SROWS * WDIM;   // horizontal 5-window sums

    const int b  = blockIdx.x >> 1;
    const int r0 = (blockIdx.x & 1) * ROWS_PER_BLK;   // first output row
    const int t  = threadIdx.x;
    const float* S = S0 + (size_t)b * N_PIX;

    // Phase A: horizontal circular window sums for rows r0-3 .. r0+66 (wrapped)
    for (int i = t; i < SROWS * WDIM; i += blockDim.x) {
        int lr = i >> 7, w = i & 127;
        int h = (r0 - HALO + lr) & (HDIM - 1);
        const float* row = S + (h << 7);
        float s7 = 0.f, s5 = 0.f;
        #pragma unroll
        for (int d = -3; d <= 3; d++) {
            float v = row[(w + d) & 127];
            s7 += v;
            if (d >= -2 && d <= 2) s5 += v;
        }
        rs7[i] = s7;
        rs5[i] = s5;
    }
    __syncthreads();

    const float decay = *p_decay, thr = *p_thr, rst = *p_reset, split = *p_split;
    const float excl = *p_excl, excg = *p_excg, inhl = *p_inhl, inhg = *p_inhg;
    const float drop = *p_drop, lower = *p_lower;
    const float w7 = *exc_w_p, w5 = *inh_w_p;       // 1/49, 1/25 (exact f32 from ref)
    const float oms = 1.0f - split;

    float* outV = out;
    float* outS = out + (size_t)BATCH * N_PIX;
    float* outY = out + (size_t)2 * BATCH * N_PIX;

    for (int i = t; i < ROWS_PER_BLK * WDIM; i += blockDim.x) {
        int lr = i >> 7, w = i & 127;
        int h = r0 + lr;

        // Phase B: vertical circular window sums from smem (conflict-free)
        float c7 = 0.f, c5 = 0.f;
        #pragma unroll
        for (int d = -3; d <= 3; d++) {
            int sr = lr + HALO + d;                   // 0..SROWS-1
            c7 += rs7[(sr << 7) + w];
            if (d >= -2 && d <= 2) c5 += rs5[(sr << 7) + w];
        }

        size_t gi = (size_t)b * N_PIX + (h << 7) + w;
        float v0 = V0[gi], u = U[gi], gg = g_global[gi];
        g_global[gi] = 0.0f;          // re-zero scratch for next launch

        // V = decay*V0 + input_split*U   (non-fused, matches XLA mul+add)
        float V = __fadd_rn(__fmul_rn(decay, v0), __fmul_rn(split, u));
        bool active = V > lower;

        // lateral = excl*conv7 + inhl*conv5 + excg*g + inhg*g
        float conv7 = __fmul_rn(c7, w7);
        float conv5 = __fmul_rn(c5, w5);
        float lat = __fadd_rn(__fmul_rn(excl, conv7), __fmul_rn(inhl, conv5));
        lat = __fadd_rn(lat, __fmul_rn(excg, gg));
        lat = __fadd_rn(lat, __fmul_rn(inhg, gg));

        if (active)
            V = __fadd_rn(__fadd_rn(V, __fmul_rn(oms, u)), lat);
        V = fminf(fmaxf(V, -2.0f), 2.0f);

        float spike = (V > thr) ? 1.0f : 0.0f;

        // deterministic dropout mask: frac(h + 0.7*w) > drop  (non-fused fp32)
        float a = __fadd_rn((float)h, __fmul_rn(0.7f, (float)w));
        float frac = __fsub_rn(a, floorf(a));
        float mask = (frac > drop) ? 1.0f : 0.0f;
        float sp = __fmul_rn(spike, mask);

        if (sp > 0.0f) V = rst;

        float y = fminf(fmaxf(__fmul_rn(__fadd_rn(V, 1.0f), 0.5f), 0.0f), 1.0f);
        y = __fadd_rn(y, __fmul_rn(0.5f, sp));
        y = fminf(fmaxf(y, 0.0f), 1.0f);

        outV[gi] = V;
        outS[gi] = sp;
        outY[gi] = y;
    }

    // Re-zero this block's slice of the spike mask (128 words per block)
    for (int i = t; i < N_PIX / (BATCH * 2); i += blockDim.x)
        g_spikemask[blockIdx.x * (N_PIX / (BATCH * 2)) + i] = 0ULL;
}

// ---------------------------------------------------------------------------
extern "C" void kernel_launch(void* const* d_in, const int* in_sizes, int n_in,
                              void* d_out, int out_size) {
    const float* V0    = (const float*)d_in[0];
    const float* S0    = (const float*)d_in[1];
    const float* U     = (const float*)d_in[2];
    const float* exc_w = (const float*)d_in[3];
    const float* inh_w = (const float*)d_in[4];
    const float* M     = (const float*)d_in[5];
    const float* decay = (const float*)d_in[6];
    const float* thr   = (const float*)d_in[7];
    const float* reset = (const float*)d_in[8];
    const float* split = (const float*)d_in[9];
    const float* excl  = (const float*)d_in[10];
    const float* excg  = (const float*)d_in[11];
    const float* inhl  = (const float*)d_in[12];
    const float* inhg  = (const float*)d_in[13];
    const float* drop  = (const float*)d_in[14];
    const float* lower = (const float*)d_in[15];
    float* out = (float*)d_out;

    prep_kernel<<<1024, 256>>>(S0);                      // mask build only
    scan_kernel<<<SCAN_BLKS, 256>>>((const float4*)M);

    int smem = 2 * SROWS * WDIM * (int)sizeof(float);    // 71,680 B
    cudaFuncSetAttribute(fused_kernel, cudaFuncAttributeMaxDynamicSharedMemorySize, smem);
    fused_kernel<<<BATCH * 2, 512, smem>>>(V0, S0, U, exc_w, inh_w,
                                           decay, thr, reset, split,
                                           excl, excg, inhl, inhg, drop, lower,
                                           out);
}

// round 5
// speedup vs baseline: 1.1031x; 1.1016x over previous
#include <cuda_runtime.h>
#include <cstdint>

#define HDIM  128
#define WDIM  128
#define N_PIX 16384          // H*W
#define BATCH 64

#define NSM        148
#define SCAN_BLKS  (NSM * 8)     // 1184 blocks, 256 thr: one full wave

// Scratch (allocation-free __device__ globals). Both are fully rewritten by
// prep_kernel at the START of every launch -> no cross-launch coupling.
__device__ unsigned long long g_spikemask[N_PIX];               // bit b set if S0[b, n] != 0
__device__ float              g_global[BATCH * (size_t)N_PIX];  // g[b][m], 4 MB

// ---------------------------------------------------------------------------
// Kernel 1: build per-pixel spike bitmask (plain disjoint uint16 stores, no
// atomics, no pre-zero needed) + zero g. Self-contained per launch.
// ---------------------------------------------------------------------------
__global__ void __launch_bounds__(256) prep_kernel(const float* __restrict__ S0) {
    int tid = blockIdx.x * blockDim.x + threadIdx.x;   // grid = 1184*256 = 303104
    int stride = gridDim.x * blockDim.x;

    if (tid < 4 * N_PIX) {                             // 65536 mask workers
        int n = tid & (N_PIX - 1);                     // pixel (coalesced in warp)
        int q = tid >> 14;                             // 16-batch chunk, 0..3
        const float* base = S0 + (size_t)(q * 16) * N_PIX + n;
        unsigned m16 = 0;
        #pragma unroll
        for (int j = 0; j < 16; j++) {                 // 16 independent coalesced loads
            float s = __ldg(base + (size_t)j * N_PIX);
            if (s != 0.0f) m16 |= (1u << j);
        }
        // little-endian halfword q of the 64-bit mask = batches [16q, 16q+16)
        reinterpret_cast<unsigned short*>(g_spikemask)[4 * n + q] = (unsigned short)m16;
    }

    // zero g with vector stores (whole grid)
    float4* g4 = reinterpret_cast<float4*>(g_global);
    const int total4 = BATCH * N_PIX / 4;
    for (int i = tid; i < total4; i += stride)
        g4[i] = make_float4(0.f, 0.f, 0.f, 0.f);
}

// ---------------------------------------------------------------------------
// Kernel 2: stream the 1 GiB matrix with 256-bit loads (sm_100a v8.f32),
// R2's grid-interleaved sweep (4 in-flight slots spaced one grid-stride).
// Scatter nonzeros into g via atomicAdd.
// ---------------------------------------------------------------------------
struct f8 { float v[8]; };

__device__ __forceinline__ f8 load8(const float* __restrict__ p) {
    f8 r;
    asm volatile("ld.global.v8.f32 {%0,%1,%2,%3,%4,%5,%6,%7}, [%8];"
                 : "=f"(r.v[0]), "=f"(r.v[1]), "=f"(r.v[2]), "=f"(r.v[3]),
                   "=f"(r.v[4]), "=f"(r.v[5]), "=f"(r.v[6]), "=f"(r.v[7])
                 : "l"(p));
    return r;
}

__device__ __forceinline__ void handle_nz(size_t idx, float val) {
    int n = (int)(idx >> 14);        // row
    int m = (int)(idx & 16383);      // col
    unsigned long long mask = g_spikemask[n];
    while (mask) {
        int b = __ffsll((long long)mask) - 1;
        atomicAdd(&g_global[(size_t)b * N_PIX + m], val);
        mask &= mask - 1;
    }
}

__device__ __forceinline__ void check8(const f8& x, size_t base) {
    unsigned nz = 0;
    #pragma unroll
    for (int j = 0; j < 8; j++) nz |= __float_as_uint(x.v[j]);
    if (nz != 0u) {
        #pragma unroll
        for (int j = 0; j < 8; j++)
            if (x.v[j] != 0.0f) handle_nz(base + j, x.v[j]);
    }
}

__global__ void __launch_bounds__(256) scan_kernel(const float* __restrict__ M) {
    const size_t total8 = (size_t)N_PIX * N_PIX / 8;       // 33,554,432 f8 units
    const size_t stride = (size_t)gridDim.x * blockDim.x;  // 303,104
    size_t i = (size_t)blockIdx.x * blockDim.x + threadIdx.x;

    // 4 independent 32B loads in flight per thread, grid-interleaved sweep
    for (; i + 3 * stride < total8; i += 4 * stride) {
        f8 a = load8(M + (i)              * 8);
        f8 b = load8(M + (i + stride)     * 8);
        f8 c = load8(M + (i + 2 * stride) * 8);
        f8 d = load8(M + (i + 3 * stride) * 8);
        check8(a, (i)              * 8);
        check8(b, (i + stride)     * 8);
        check8(c, (i + 2 * stride) * 8);
        check8(d, (i + 3 * stride) * 8);
    }
    for (; i < total8; i += stride) {
        f8 a = load8(M + i * 8);
        check8(a, i * 8);
    }
}

// ---------------------------------------------------------------------------
// Kernel 3: box convs (separable circular window sums) + fused update.
// Two blocks per batch (64 rows + 3-row halo). No scratch mutation here.
// ---------------------------------------------------------------------------
#define ROWS_PER_BLK 64
#define HALO 3
#define SROWS (ROWS_PER_BLK + 2 * HALO)   // 70

__global__ void fused_kernel(
    const float* __restrict__ V0, const float* __restrict__ S0,
    const float* __restrict__ U,
    const float* __restrict__ exc_w_p, const float* __restrict__ inh_w_p,
    const float* __restrict__ p_decay, const float* __restrict__ p_thr,
    const float* __restrict__ p_reset, const float* __restrict__ p_split,
    const float* __restrict__ p_excl,  const float* __restrict__ p_excg,
    const float* __restrict__ p_inhl,  const float* __restrict__ p_inhg,
    const float* __restrict__ p_drop,  const float* __restrict__ p_lower,
    float* __restrict__ out)
{
    extern __shared__ float sm[];
    float* rs7 = sm;                  // horizontal 7-window sums, SROWS x 128
    float* rs5 = sm + SROWS * WDIM;   // horizontal 5-window sums

    const int b  = blockIdx.x >> 1;
    const int r0 = (blockIdx.x & 1) * ROWS_PER_BLK;   // first output row
    const int t  = threadIdx.x;
    const float* S = S0 + (size_t)b * N_PIX;

    // Phase A: horizontal circular window sums for rows r0-3 .. r0+66 (wrapped)
    for (int i = t; i < SROWS * WDIM; i += blockDim.x) {
        int lr = i >> 7, w = i & 127;
        int h = (r0 - HALO + lr) & (HDIM - 1);
        const float* row = S + (h << 7);
        float s7 = 0.f, s5 = 0.f;
        #pragma unroll
        for (int d = -3; d <= 3; d++) {
            float v = row[(w + d) & 127];
            s7 += v;
            if (d >= -2 && d <= 2) s5 += v;
        }
        rs7[i] = s7;
        rs5[i] = s5;
    }
    __syncthreads();

    const float decay = *p_decay, thr = *p_thr, rst = *p_reset, split = *p_split;
    const float excl = *p_excl, excg = *p_excg, inhl = *p_inhl, inhg = *p_inhg;
    const float drop = *p_drop, lower = *p_lower;
    const float w7 = *exc_w_p, w5 = *inh_w_p;       // 1/49, 1/25 (exact f32 from ref)
    const float oms = 1.0f - split;

    float* outV = out;
    float* outS = out + (size_t)BATCH * N_PIX;
    float* outY = out + (size_t)2 * BATCH * N_PIX;

    for (int i = t; i < ROWS_PER_BLK * WDIM; i += blockDim.x) {
        int lr = i >> 7, w = i & 127;
        int h = r0 + lr;

        // Phase B: vertical circular window sums from smem (conflict-free)
        float c7 = 0.f, c5 = 0.f;
        #pragma unroll
        for (int d = -3; d <= 3; d++) {
            int sr = lr + HALO + d;                   // 0..SROWS-1
            c7 += rs7[(sr << 7) + w];
            if (d >= -2 && d <= 2) c5 += rs5[(sr << 7) + w];
        }

        size_t gi = (size_t)b * N_PIX + (h << 7) + w;
        float v0 = V0[gi], u = U[gi], gg = g_global[gi];

        // V = decay*V0 + input_split*U   (non-fused, matches XLA mul+add)
        float V = __fadd_rn(__fmul_rn(decay, v0), __fmul_rn(split, u));
        bool active = V > lower;

        // lateral = excl*conv7 + inhl*conv5 + excg*g + inhg*g
        float conv7 = __fmul_rn(c7, w7);
        float conv5 = __fmul_rn(c5, w5);
        float lat = __fadd_rn(__fmul_rn(excl, conv7), __fmul_rn(inhl, conv5));
        lat = __fadd_rn(lat, __fmul_rn(excg, gg));
        lat = __fadd_rn(lat, __fmul_rn(inhg, gg));

        if (active)
            V = __fadd_rn(__fadd_rn(V, __fmul_rn(oms, u)), lat);
        V = fminf(fmaxf(V, -2.0f), 2.0f);

        float spike = (V > thr) ? 1.0f : 0.0f;

        // deterministic dropout mask: frac(h + 0.7*w) > drop  (non-fused fp32)
        float a = __fadd_rn((float)h, __fmul_rn(0.7f, (float)w));
        float frac = __fsub_rn(a, floorf(a));
        float mask = (frac > drop) ? 1.0f : 0.0f;
        float sp = __fmul_rn(spike, mask);

        if (sp > 0.0f) V = rst;

        float y = fminf(fmaxf(__fmul_rn(__fadd_rn(V, 1.0f), 0.5f), 0.0f), 1.0f);
        y = __fadd_rn(y, __fmul_rn(0.5f, sp));
        y = fminf(fmaxf(y, 0.0f), 1.0f);

        outV[gi] = V;
        outS[gi] = sp;
        outY[gi] = y;
    }
}

// ---------------------------------------------------------------------------
extern "C" void kernel_launch(void* const* d_in, const int* in_sizes, int n_in,
                              void* d_out, int out_size) {
    const float* V0    = (const float*)d_in[0];
    const float* S0    = (const float*)d_in[1];
    const float* U     = (const float*)d_in[2];
    const float* exc_w = (const float*)d_in[3];
    const float* inh_w = (const float*)d_in[4];
    const float* M     = (const float*)d_in[5];
    const float* decay = (const float*)d_in[6];
    const float* thr   = (const float*)d_in[7];
    const float* reset = (const float*)d_in[8];
    const float* split = (const float*)d_in[9];
    const float* excl  = (const float*)d_in[10];
    const float* excg  = (const float*)d_in[11];
    const float* inhl  = (const float*)d_in[12];
    const float* inhg  = (const float*)d_in[13];
    const float* drop  = (const float*)d_in[14];
    const float* lower = (const float*)d_in[15];
    float* out = (float*)d_out;

    prep_kernel<<<SCAN_BLKS, 256>>>(S0);
    scan_kernel<<<SCAN_BLKS, 256>>>(M);

    int smem = 2 * SROWS * WDIM * (int)sizeof(float);    // 71,680 B
    cudaFuncSetAttribute(fused_kernel, cudaFuncAttributeMaxDynamicSharedMemorySize, smem);
    fused_kernel<<<BATCH * 2, 512, smem>>>(V0, S0, U, exc_w, inh_w,
                                           decay, thr, reset, split,
                                           excl, excg, inhl, inhg, drop, lower,
                                           out);
}